// round 15
// baseline (speedup 1.0000x reference)
#include <cuda_runtime.h>
#include <cuda_fp16.h>
#include <cstdint>

// ---------------------------------------------------------------------------
// Problem constants
// ---------------------------------------------------------------------------
constexpr int B   = 2;
constexpr int S   = 2048;
constexpr int H   = 2048;
constexpr int NH  = 16;
constexpr int D   = 128;
constexpr int M   = B * S;     // 4096
constexpr int H3  = 3 * H;     // 6144
constexpr float SM_SCALE = 0.08838834764831845f;  // 1/sqrt(128)

// ---------------------------------------------------------------------------
// Scratch (fp16 operands; fp32 only at the final output)
// ---------------------------------------------------------------------------
__device__ __half g_qkv[(size_t)M * H3];     // [4096, 6144]
__device__ __half g_ctx[(size_t)M * H];      // [4096, 2048]
__device__ __half g_ah [(size_t)M * H];      // hidden -> fp16
__device__ __half g_wqkvt[(size_t)H3 * H];   // W_qkv^T [6144][2048]
__device__ __half g_woutt[(size_t)H * H];    // W_out^T [2048][2048]

// ---------------------------------------------------------------------------
// Helpers (baseline PTX only — compiles at compute_100)
// ---------------------------------------------------------------------------
__device__ __forceinline__ uint32_t smem_u32(const void* p) {
    uint32_t a;
    asm("{ .reg .u64 t; cvta.to.shared.u64 t, %1; cvt.u32.u64 %0, t; }"
        : "=r"(a) : "l"(p));
    return a;
}
// fp16 mma: D(16x8,f32) = A(16x16,f16) * B(16x8,f16) + C.
// b0/b1 passed as scalars (no temp array -> no MOVs).
__device__ __forceinline__ void mma16(float* d, const uint32_t* a,
                                      uint32_t b0, uint32_t b1) {
    asm volatile(
        "mma.sync.aligned.m16n8k16.row.col.f32.f16.f16.f32 "
        "{%0,%1,%2,%3}, {%4,%5,%6,%7}, {%8,%9}, {%0,%1,%2,%3};\n"
        : "+f"(d[0]), "+f"(d[1]), "+f"(d[2]), "+f"(d[3])
        : "r"(a[0]), "r"(a[1]), "r"(a[2]), "r"(a[3]), "r"(b0), "r"(b1));
}
// x4 ldmatrix b16.  lane addr = base + ((lane&7)+(lane&8))*stride + ((lane&16)?8:0)
// plain on [row][k]: A-frag (row=m) or plain-B pairs (row=n; n-oct even {r0,r2}, odd {r1,r3})
// trans on [k][col]: B-frag (d-oct even {r0,r1}, odd {r2,r3})
__device__ __forceinline__ void ldm_x4(uint32_t* r, uint32_t addr) {
    asm volatile("ldmatrix.sync.aligned.m8n8.x4.shared.b16 {%0,%1,%2,%3}, [%4];"
                 : "=r"(r[0]), "=r"(r[1]), "=r"(r[2]), "=r"(r[3]) : "r"(addr));
}
__device__ __forceinline__ void ldm_x4_t(uint32_t* r, uint32_t addr) {
    asm volatile("ldmatrix.sync.aligned.m8n8.x4.trans.shared.b16 {%0,%1,%2,%3}, [%4];"
                 : "=r"(r[0]), "=r"(r[1]), "=r"(r[2]), "=r"(r[3]) : "r"(addr));
}
__device__ __forceinline__ void cp_async16(void* smem, const void* gmem) {
    uint32_t s = (uint32_t)__cvta_generic_to_shared(smem);
    asm volatile("cp.async.cg.shared.global [%0], [%1], 16;\n" :: "r"(s), "l"(gmem));
}
__device__ __forceinline__ void cp_commit() { asm volatile("cp.async.commit_group;\n"); }
template <int N>
__device__ __forceinline__ void cp_wait() {
    asm volatile("cp.async.wait_group %0;\n" :: "n"(N));
}

// ---------------------------------------------------------------------------
// Prologue 1: fp32 -> fp16 (hidden -> g_ah)
// ---------------------------------------------------------------------------
__global__ void conv_half_kernel(const float* __restrict__ in,
                                 __half* __restrict__ out, int n8)
{
    int i = blockIdx.x * 256 + threadIdx.x;
    if (i < n8) {
        float4 v0 = reinterpret_cast<const float4*>(in)[2 * i];
        float4 v1 = reinterpret_cast<const float4*>(in)[2 * i + 1];
        __half2 h[4];
        h[0] = __floats2half2_rn(v0.x, v0.y);
        h[1] = __floats2half2_rn(v0.z, v0.w);
        h[2] = __floats2half2_rn(v1.x, v1.y);
        h[3] = __floats2half2_rn(v1.z, v1.w);
        reinterpret_cast<uint2*>(out)[2 * i]     = *reinterpret_cast<uint2*>(&h[0]);
        reinterpret_cast<uint2*>(out)[2 * i + 1] = *reinterpret_cast<uint2*>(&h[2]);
    }
}

// ---------------------------------------------------------------------------
// Prologue 2: W [K][N] fp32 -> Wt [N][K] fp16.  block (32,8)
// ---------------------------------------------------------------------------
__global__ void transpose_half_kernel(const float* __restrict__ W,
                                      __half* __restrict__ Wt, int K, int N)
{
    __shared__ float t[32][33];
    const int n0 = blockIdx.x * 32, k0 = blockIdx.y * 32;
    const int tx = threadIdx.x, ty = threadIdx.y;
#pragma unroll
    for (int j = 0; j < 4; j++)
        t[ty + 8 * j][tx] = W[(size_t)(k0 + ty + 8 * j) * N + n0 + tx];
    __syncthreads();
#pragma unroll
    for (int j = 0; j < 4; j++)
        Wt[(size_t)(n0 + ty + 8 * j) * K + k0 + tx] = __float2half_rn(t[tx][ty + 8 * j]);
}

// ---------------------------------------------------------------------------
// fp16 GEMM v2 (QKV): C[128m x 128n per CTA], 4 warps each 64x64.
// k-chunk 64, 2-stage cp.async, ldmatrix x4, 8 ldm per 32 mma.
// smem stride 72 halfs; 73728 B total; launch_bounds(128,3) -> 3 CTAs/SM.
// ---------------------------------------------------------------------------
constexpr int SAH = 72;                       // halfs per row
constexpr int G2A = 128 * SAH;                // A tile halfs
constexpr int G2STG = 2 * G2A;                // A + B per stage
constexpr int G2SMEM_BYTES = 2 * G2STG * 2;   // 73728 B

__global__ __launch_bounds__(128, 3)
void gemm_h128_kernel(const __half* __restrict__ A,  int lda,
                      const __half* __restrict__ Bt, int ldbt,
                      void* __restrict__ Cv,         int ldc,
                      int K, const float* __restrict__ bias, int out_half)
{
    extern __shared__ __align__(16) __half sg[];

    const int tid  = threadIdx.x;
    const int warp = tid >> 5, lane = tid & 31;
    const int g = lane >> 2, t = lane & 3;
    const int wm = (warp >> 1) * 64, wn = (warp & 1) * 64;
    const int m0 = blockIdx.y * 128, n0 = blockIdx.x * 128;

    A  += (size_t)m0 * lda;
    Bt += (size_t)n0 * ldbt;

    const int rowL = (lane & 7) + (lane & 8);
    const int colL = (lane & 16) ? 8 : 0;

    float acc[4][8][4];
#pragma unroll
    for (int mi = 0; mi < 4; mi++)
#pragma unroll
        for (int nj = 0; nj < 8; nj++)
#pragma unroll
            for (int r = 0; r < 4; r++) acc[mi][nj][r] = 0.0f;

    auto stage = [&](int kt, int buf) {
        __half* dA = sg + buf * G2STG;
        __half* dB = dA + G2A;
        const int k0 = kt * 64;
#pragma unroll
        for (int j = 0; j < 8; j++) {              // A: 1024 chunks
            int idx = tid + j * 128;
            int r = idx >> 3, c = (idx & 7) * 8;
            cp_async16(&dA[r * SAH + c], A + (size_t)r * lda + k0 + c);
        }
#pragma unroll
        for (int j = 0; j < 8; j++) {              // B: 1024 chunks
            int idx = tid + j * 128;
            int r = idx >> 3, c = (idx & 7) * 8;
            cp_async16(&dB[r * SAH + c], Bt + (size_t)r * ldbt + k0 + c);
        }
        cp_commit();
    };

    stage(0, 0);
    const int KT = K / 64;

    for (int kt = 0; kt < KT; kt++) {
        const int buf = kt & 1;
        if (kt + 1 < KT) { stage(kt + 1, buf ^ 1); cp_wait<1>(); }
        else             { cp_wait<0>(); }
        __syncthreads();

        const __half* cA = sg + buf * G2STG;
        const __half* cB = cA + G2A;
        uint32_t aAdr[4], bAdr[4];
#pragma unroll
        for (int mi = 0; mi < 4; mi++)
            aAdr[mi] = smem_u32(cA + (wm + mi * 16 + rowL) * SAH + colL);
#pragma unroll
        for (int njp = 0; njp < 4; njp++)
            bAdr[njp] = smem_u32(cB + (wn + njp * 16 + rowL) * SAH + colL);

#pragma unroll
        for (int kk = 0; kk < 64; kk += 16) {
            uint32_t a[4][4], bfr[4][4];
#pragma unroll
            for (int mi = 0; mi < 4; mi++)   ldm_x4(a[mi],   aAdr[mi]  + kk * 2);
#pragma unroll
            for (int njp = 0; njp < 4; njp++) ldm_x4(bfr[njp], bAdr[njp] + kk * 2);
#pragma unroll
            for (int mi = 0; mi < 4; mi++)
#pragma unroll
                for (int nj = 0; nj < 8; nj++)
                    mma16(acc[mi][nj], a[mi],
                          bfr[nj >> 1][nj & 1], bfr[nj >> 1][(nj & 1) + 2]);
        }
        __syncthreads();
    }

    // epilogue
#pragma unroll
    for (int mi = 0; mi < 4; mi++) {
#pragma unroll
        for (int nj = 0; nj < 8; nj++) {
            const int row = wm + mi * 16 + g;
            const int col = wn + nj * 8 + 2 * t;
            const float b0 = bias ? bias[n0 + col]     : 0.0f;
            const float b1 = bias ? bias[n0 + col + 1] : 0.0f;
            float v0 = acc[mi][nj][0] + b0, v1 = acc[mi][nj][1] + b1;
            float v2 = acc[mi][nj][2] + b0, v3 = acc[mi][nj][3] + b1;
            if (out_half) {
                __half* C16 = (__half*)Cv + (size_t)m0 * ldc + n0;
                *reinterpret_cast<__half2*>(C16 + (size_t)row * ldc + col) =
                    __floats2half2_rn(v0, v1);
                *reinterpret_cast<__half2*>(C16 + (size_t)(row + 8) * ldc + col) =
                    __floats2half2_rn(v2, v3);
            } else {
                float* C32 = (float*)Cv + (size_t)m0 * ldc + n0;
                *reinterpret_cast<float2*>(C32 + (size_t)row * ldc + col) =
                    make_float2(v0, v1);
                *reinterpret_cast<float2*>(C32 + (size_t)(row + 8) * ldc + col) =
                    make_float2(v2, v3);
            }
        }
    }
}

// ---------------------------------------------------------------------------
// fp16 GEMM (out-proj, round-14 verified shape): C[128m x 64n], 4 CTAs/SM.
// Only change: direct b-operand pass.
// ---------------------------------------------------------------------------
constexpr int GA  = 128 * SAH;
constexpr int GB  = 64 * SAH;
constexpr int GSTG = GA + GB;
constexpr int GSMEM_BYTES = 2 * GSTG * 2;     // 55296 B

__global__ __launch_bounds__(128, 4)
void gemm_h_kernel(const __half* __restrict__ A,  int lda,
                   const __half* __restrict__ Bt, int ldbt,
                   void* __restrict__ Cv,         int ldc,
                   int K, const float* __restrict__ bias, int out_half)
{
    extern __shared__ __align__(16) __half sg[];

    const int tid  = threadIdx.x;
    const int warp = tid >> 5, lane = tid & 31;
    const int g = lane >> 2, t = lane & 3;
    const int wm = (warp >> 1) * 64, wn = (warp & 1) * 32;
    const int m0 = blockIdx.y * 128, n0 = blockIdx.x * 64;

    A  += (size_t)m0 * lda;
    Bt += (size_t)n0 * ldbt;

    const int rowL = (lane & 7) + (lane & 8);
    const int colL = (lane & 16) ? 8 : 0;

    float acc[4][4][4];
#pragma unroll
    for (int mi = 0; mi < 4; mi++)
#pragma unroll
        for (int nj = 0; nj < 4; nj++)
#pragma unroll
            for (int r = 0; r < 4; r++) acc[mi][nj][r] = 0.0f;

    auto stage = [&](int kt, int buf) {
        __half* dA = sg + buf * GSTG;
        __half* dB = dA + GA;
        const int k0 = kt * 64;
#pragma unroll
        for (int j = 0; j < 8; j++) {
            int idx = tid + j * 128;
            int r = idx >> 3, c = (idx & 7) * 8;
            cp_async16(&dA[r * SAH + c], A + (size_t)r * lda + k0 + c);
        }
#pragma unroll
        for (int j = 0; j < 4; j++) {
            int idx = tid + j * 128;
            int r = idx >> 3, c = (idx & 7) * 8;
            cp_async16(&dB[r * SAH + c], Bt + (size_t)r * ldbt + k0 + c);
        }
        cp_commit();
    };

    stage(0, 0);
    const int KT = K / 64;

    for (int kt = 0; kt < KT; kt++) {
        const int buf = kt & 1;
        if (kt + 1 < KT) { stage(kt + 1, buf ^ 1); cp_wait<1>(); }
        else             { cp_wait<0>(); }
        __syncthreads();

        const __half* cA = sg + buf * GSTG;
        const __half* cB = cA + GA;
        uint32_t aAdr[4], bAdr[2];
#pragma unroll
        for (int mi = 0; mi < 4; mi++)
            aAdr[mi] = smem_u32(cA + (wm + mi * 16 + rowL) * SAH + colL);
#pragma unroll
        for (int njp = 0; njp < 2; njp++)
            bAdr[njp] = smem_u32(cB + (wn + njp * 16 + rowL) * SAH + colL);

#pragma unroll
        for (int kk = 0; kk < 64; kk += 16) {
            uint32_t a[4][4], bfr[2][4];
#pragma unroll
            for (int mi = 0; mi < 4; mi++)   ldm_x4(a[mi],   aAdr[mi]  + kk * 2);
#pragma unroll
            for (int njp = 0; njp < 2; njp++) ldm_x4(bfr[njp], bAdr[njp] + kk * 2);
#pragma unroll
            for (int mi = 0; mi < 4; mi++)
#pragma unroll
                for (int nj = 0; nj < 4; nj++)
                    mma16(acc[mi][nj], a[mi],
                          bfr[nj >> 1][nj & 1], bfr[nj >> 1][(nj & 1) + 2]);
        }
        __syncthreads();
    }

#pragma unroll
    for (int mi = 0; mi < 4; mi++) {
#pragma unroll
        for (int nj = 0; nj < 4; nj++) {
            const int row = wm + mi * 16 + g;
            const int col = wn + nj * 8 + 2 * t;
            const float b0 = bias ? bias[n0 + col]     : 0.0f;
            const float b1 = bias ? bias[n0 + col + 1] : 0.0f;
            float v0 = acc[mi][nj][0] + b0, v1 = acc[mi][nj][1] + b1;
            float v2 = acc[mi][nj][2] + b0, v3 = acc[mi][nj][3] + b1;
            if (out_half) {
                __half* C16 = (__half*)Cv + (size_t)m0 * ldc + n0;
                *reinterpret_cast<__half2*>(C16 + (size_t)row * ldc + col) =
                    __floats2half2_rn(v0, v1);
                *reinterpret_cast<__half2*>(C16 + (size_t)(row + 8) * ldc + col) =
                    __floats2half2_rn(v2, v3);
            } else {
                float* C32 = (float*)Cv + (size_t)m0 * ldc + n0;
                *reinterpret_cast<float2*>(C32 + (size_t)row * ldc + col) =
                    make_float2(v0, v1);
                *reinterpret_cast<float2*>(C32 + (size_t)(row + 8) * ldc + col) =
                    make_float2(v2, v3);
            }
        }
    }
}

// ---------------------------------------------------------------------------
// Fused flash attention, fp16 (round-14 verified; byte-identical logic).
// ---------------------------------------------------------------------------
constexpr int FQ = 64;
constexpr int FP = 136;
constexpr int FLASH_SMEM_BYTES =
    (FQ * FP + 128 * FP + 128 * FP + FQ * FP) * 2 + (FQ + S) * 4;  // ~113 KB

__global__ __launch_bounds__(256, 2)
void flash_h_kernel(const float* __restrict__ mask)
{
    extern __shared__ __align__(16) __half smh[];
    __half* sQ = smh;
    __half* sK = sQ + FQ * FP;
    __half* sV = sK + 128 * FP;
    __half* sP = sV + 128 * FP;
    float* sRow  = reinterpret_cast<float*>(sP + FQ * FP);
    float* sMask = sRow + FQ;

    const int tid  = threadIdx.x;
    const int warp = tid >> 5, lane = tid & 31;
    const int g = lane >> 2, t = lane & 3;
    const int wm = (warp >> 2) * 32;
    const int wn = (warp & 3) * 32;

    const int rowL = (lane & 7) + (lane & 8);
    const int colL = (lane & 16) ? 8 : 0;

    const int z  = blockIdx.y;
    const int b  = z >> 4;
    const int h  = z & 15;
    const int q0 = blockIdx.x * FQ;

    const __half* __restrict__ Qg = g_qkv + (size_t)(b * S + q0) * H3 + h * D;

#pragma unroll
    for (int j = 0; j < 4; j++) {
        int idx = tid + j * 256;
        int r = idx >> 4, c = (idx & 15) * 8;
        cp_async16(&sQ[r * FP + c], Qg + (size_t)r * H3 + c);
    }
    {
        const __half* Kg0 = g_qkv + (size_t)(b * S) * H3 + H + h * D;
#pragma unroll
        for (int j = 0; j < 8; j++) {
            int idx = tid + j * 256;
            int r = idx >> 4, c = (idx & 15) * 8;
            cp_async16(&sK[r * FP + c], Kg0 + (size_t)r * H3 + c);
        }
    }
    cp_commit();
#pragma unroll
    for (int i = tid; i < S; i += 256) sMask[i] = mask[(size_t)b * S + i];
    if (tid < FQ) sRow[tid] = 0.0f;

    uint32_t aQAdr[2], aPAdr[2], bKAdr[2], bVAdr[2];
#pragma unroll
    for (int mi = 0; mi < 2; mi++) {
        aQAdr[mi] = smem_u32(sQ + (wm + mi * 16 + rowL) * FP + colL);
        aPAdr[mi] = smem_u32(sP + (wm + mi * 16 + rowL) * FP + colL);
    }
#pragma unroll
    for (int njp = 0; njp < 2; njp++) {
        bKAdr[njp] = smem_u32(sK + (wn + njp * 16 + rowL) * FP + colL);
        bVAdr[njp] = smem_u32(sV + rowL * FP + wn + njp * 16 + colL);
    }

    float oacc[2][4][4];
#pragma unroll
    for (int mi = 0; mi < 2; mi++)
#pragma unroll
        for (int nj = 0; nj < 4; nj++)
#pragma unroll
            for (int r = 0; r < 4; r++) oacc[mi][nj][r] = 0.0f;

    for (int jt = 0; jt < S / 128; jt++) {
        const int n0 = jt * 128;

        cp_wait<0>();
        __syncthreads();

        {
            const __half* Vg = g_qkv + (size_t)(b * S + n0) * H3 + 2 * H + h * D;
#pragma unroll
            for (int j = 0; j < 8; j++) {
                int idx = tid + j * 256;
                int r = idx >> 4, c = (idx & 15) * 8;
                cp_async16(&sV[r * FP + c], Vg + (size_t)r * H3 + c);
            }
            cp_commit();
        }

        float sacc[2][4][4];
#pragma unroll
        for (int mi = 0; mi < 2; mi++)
#pragma unroll
            for (int nj = 0; nj < 4; nj++)
#pragma unroll
                for (int r = 0; r < 4; r++) sacc[mi][nj][r] = 0.0f;

#pragma unroll
        for (int kk = 0; kk < D; kk += 16) {
            uint32_t a[2][4], bfr[2][4];
#pragma unroll
            for (int mi = 0; mi < 2; mi++)   ldm_x4(a[mi],   aQAdr[mi] + kk * 2);
#pragma unroll
            for (int njp = 0; njp < 2; njp++) ldm_x4(bfr[njp], bKAdr[njp] + kk * 2);
#pragma unroll
            for (int mi = 0; mi < 2; mi++)
#pragma unroll
                for (int nj = 0; nj < 4; nj++)
                    mma16(sacc[mi][nj], a[mi],
                          bfr[nj >> 1][nj & 1], bfr[nj >> 1][(nj & 1) + 2]);
        }

#pragma unroll
        for (int mi = 0; mi < 2; mi++) {
            const int r0 = wm + mi * 16 + g;
            float rp0 = 0.0f, rp1 = 0.0f;
#pragma unroll
            for (int nj = 0; nj < 4; nj++) {
                const int col = wn + nj * 8 + 2 * t;
                const float m0v = sMask[n0 + col];
                const float m1v = sMask[n0 + col + 1];
                float p00 = __expf(fmaf(sacc[mi][nj][0], SM_SCALE, m0v));
                float p01 = __expf(fmaf(sacc[mi][nj][1], SM_SCALE, m1v));
                float p10 = __expf(fmaf(sacc[mi][nj][2], SM_SCALE, m0v));
                float p11 = __expf(fmaf(sacc[mi][nj][3], SM_SCALE, m1v));
                rp0 += p00 + p01;
                rp1 += p10 + p11;
                *reinterpret_cast<__half2*>(&sP[r0 * FP + col]) =
                    __floats2half2_rn(p00, p01);
                *reinterpret_cast<__half2*>(&sP[(r0 + 8) * FP + col]) =
                    __floats2half2_rn(p10, p11);
            }
            rp0 += __shfl_xor_sync(0xffffffffu, rp0, 1);
            rp0 += __shfl_xor_sync(0xffffffffu, rp0, 2);
            rp1 += __shfl_xor_sync(0xffffffffu, rp1, 1);
            rp1 += __shfl_xor_sync(0xffffffffu, rp1, 2);
            if (t == 0) {
                atomicAdd(&sRow[r0], rp0);
                atomicAdd(&sRow[r0 + 8], rp1);
            }
        }

        cp_wait<0>();
        __syncthreads();

        if (jt + 1 < S / 128) {
            const __half* Kg = g_qkv + (size_t)(b * S + n0 + 128) * H3 + H + h * D;
#pragma unroll
            for (int j = 0; j < 8; j++) {
                int idx = tid + j * 256;
                int r = idx >> 4, c = (idx & 15) * 8;
                cp_async16(&sK[r * FP + c], Kg + (size_t)r * H3 + c);
            }
            cp_commit();
        }

#pragma unroll
        for (int kk = 0; kk < 128; kk += 16) {
            uint32_t a[2][4], bfr[2][4];
#pragma unroll
            for (int mi = 0; mi < 2; mi++) ldm_x4(a[mi], aPAdr[mi] + kk * 2);
#pragma unroll
            for (int njp = 0; njp < 2; njp++)
                ldm_x4_t(bfr[njp], bVAdr[njp] + kk * (FP * 2));
#pragma unroll
            for (int mi = 0; mi < 2; mi++)
#pragma unroll
                for (int nj = 0; nj < 4; nj++)
                    mma16(oacc[mi][nj], a[mi],
                          bfr[nj >> 1][(nj & 1) * 2], bfr[nj >> 1][(nj & 1) * 2 + 1]);
        }
    }

#pragma unroll
    for (int mi = 0; mi < 2; mi++) {
        const int r0 = wm + mi * 16 + g;
        const float inv0 = 1.0f / sRow[r0];
        const float inv1 = 1.0f / sRow[r0 + 8];
#pragma unroll
        for (int nj = 0; nj < 4; nj++) {
            const int col = wn + nj * 8 + 2 * t;
            __half* dst = g_ctx + (size_t)(b * S + q0 + r0) * H + h * D + col;
            *reinterpret_cast<__half2*>(dst) =
                __floats2half2_rn(oacc[mi][nj][0] * inv0, oacc[mi][nj][1] * inv0);
            *reinterpret_cast<__half2*>(dst + (size_t)8 * H) =
                __floats2half2_rn(oacc[mi][nj][2] * inv1, oacc[mi][nj][3] * inv1);
        }
    }
}

// ---------------------------------------------------------------------------
// Launch
// ---------------------------------------------------------------------------
extern "C" void kernel_launch(void* const* d_in, const int* in_sizes, int n_in,
                              void* d_out, int out_size)
{
    const float* hidden = nullptr;
    const float* mask   = nullptr;
    const float* W_qkv  = nullptr;
    const float* b_qkv  = nullptr;
    const float* W_out  = nullptr;
    const float* b_out  = nullptr;

    for (int i = 0; i < n_in; i++) {
        switch (in_sizes[i]) {
            case 8388608:  hidden = (const float*)d_in[i]; break;
            case 4096:     mask   = (const float*)d_in[i]; break;
            case 12582912: W_qkv  = (const float*)d_in[i]; break;
            case 6144:     b_qkv  = (const float*)d_in[i]; break;
            case 4194304:  W_out  = (const float*)d_in[i]; break;
            case 2048:     b_out  = (const float*)d_in[i]; break;
            default: break;
        }
    }
    float* out = (float*)d_out;

    cudaFuncSetAttribute(flash_h_kernel,
                         cudaFuncAttributeMaxDynamicSharedMemorySize,
                         FLASH_SMEM_BYTES);
    cudaFuncSetAttribute(gemm_h_kernel,
                         cudaFuncAttributeMaxDynamicSharedMemorySize,
                         GSMEM_BYTES);
    cudaFuncSetAttribute(gemm_h128_kernel,
                         cudaFuncAttributeMaxDynamicSharedMemorySize,
                         G2SMEM_BYTES);

    __half* qkv_ptr;   cudaGetSymbolAddress((void**)&qkv_ptr,  g_qkv);
    __half* ctx_ptr;   cudaGetSymbolAddress((void**)&ctx_ptr,  g_ctx);
    __half* ah_ptr;    cudaGetSymbolAddress((void**)&ah_ptr,   g_ah);
    __half* wqkvt_ptr; cudaGetSymbolAddress((void**)&wqkvt_ptr, g_wqkvt);
    __half* woutt_ptr; cudaGetSymbolAddress((void**)&woutt_ptr, g_woutt);

    conv_half_kernel<<<(M * H / 8 + 255) / 256, 256>>>(hidden, ah_ptr, M * H / 8);
    transpose_half_kernel<<<dim3(H3 / 32, H / 32), dim3(32, 8)>>>(W_qkv, wqkvt_ptr, H, H3);
    transpose_half_kernel<<<dim3(H / 32, H / 32), dim3(32, 8)>>>(W_out, woutt_ptr, H, H);

    // QKV projection (fp16 output): 128x128 CTA kernel
    gemm_h128_kernel<<<dim3(H3 / 128, M / 128), 128, G2SMEM_BYTES>>>(
        ah_ptr, H, wqkvt_ptr, H, qkv_ptr, H3, H, b_qkv, 1);

    flash_h_kernel<<<dim3(S / FQ, B * NH), 256, FLASH_SMEM_BYTES>>>(mask);

    // output projection (fp32 output): 128x64 CTA kernel, tail-friendly grid
    gemm_h_kernel<<<dim3(H / 64, M / 128), 128, GSMEM_BYTES>>>(
        ctx_ptr, H, woutt_ptr, H, out, H, H, b_out, 0);
}

// round 16
// speedup vs baseline: 1.0025x; 1.0025x over previous
#include <cuda_runtime.h>
#include <cuda_fp16.h>
#include <cstdint>

// ---------------------------------------------------------------------------
// Problem constants
// ---------------------------------------------------------------------------
constexpr int B   = 2;
constexpr int S   = 2048;
constexpr int H   = 2048;
constexpr int NH  = 16;
constexpr int D   = 128;
constexpr int M   = B * S;     // 4096
constexpr int H3  = 3 * H;     // 6144
constexpr float SM_SCALE = 0.08838834764831845f;  // 1/sqrt(128)

// ---------------------------------------------------------------------------
// Scratch (fp16 operands; fp32 only at the final output)
// ---------------------------------------------------------------------------
__device__ __half g_qkv[(size_t)M * H3];     // [4096, 6144]
__device__ __half g_ctx[(size_t)M * H];      // [4096, 2048]
__device__ __half g_ah [(size_t)M * H];      // hidden -> fp16
__device__ __half g_wqkvt[(size_t)H3 * H];   // W_qkv^T [6144][2048]
__device__ __half g_woutt[(size_t)H * H];    // W_out^T [2048][2048]

// ---------------------------------------------------------------------------
// Helpers (baseline PTX only — compiles at compute_100)
// ---------------------------------------------------------------------------
__device__ __forceinline__ uint32_t smem_u32(const void* p) {
    uint32_t a;
    asm("{ .reg .u64 t; cvta.to.shared.u64 t, %1; cvt.u32.u64 %0, t; }"
        : "=r"(a) : "l"(p));
    return a;
}
// fp16 mma: D(16x8,f32) = A(16x16,f16) * B(16x8,f16) + C.  Scalar b operands.
__device__ __forceinline__ void mma16(float* d, const uint32_t* a,
                                      uint32_t b0, uint32_t b1) {
    asm volatile(
        "mma.sync.aligned.m16n8k16.row.col.f32.f16.f16.f32 "
        "{%0,%1,%2,%3}, {%4,%5,%6,%7}, {%8,%9}, {%0,%1,%2,%3};\n"
        : "+f"(d[0]), "+f"(d[1]), "+f"(d[2]), "+f"(d[3])
        : "r"(a[0]), "r"(a[1]), "r"(a[2]), "r"(a[3]), "r"(b0), "r"(b1));
}
// x4 ldmatrix b16.  lane addr = base + ((lane&7)+(lane&8))*stride + ((lane&16)?8:0)
// plain on [row][k]: A-frag (row=m) or plain-B pairs (row=n; n-oct even {r0,r2}, odd {r1,r3})
// trans on [k][col]: B-frag (d-oct even {r0,r1}, odd {r2,r3})
__device__ __forceinline__ void ldm_x4(uint32_t* r, uint32_t addr) {
    asm volatile("ldmatrix.sync.aligned.m8n8.x4.shared.b16 {%0,%1,%2,%3}, [%4];"
                 : "=r"(r[0]), "=r"(r[1]), "=r"(r[2]), "=r"(r[3]) : "r"(addr));
}
__device__ __forceinline__ void ldm_x4_t(uint32_t* r, uint32_t addr) {
    asm volatile("ldmatrix.sync.aligned.m8n8.x4.trans.shared.b16 {%0,%1,%2,%3}, [%4];"
                 : "=r"(r[0]), "=r"(r[1]), "=r"(r[2]), "=r"(r[3]) : "r"(addr));
}
__device__ __forceinline__ void cp_async16s(uint32_t smem, const void* gmem) {
    asm volatile("cp.async.cg.shared.global [%0], [%1], 16;\n" :: "r"(smem), "l"(gmem));
}
__device__ __forceinline__ void cp_commit() { asm volatile("cp.async.commit_group;\n"); }
template <int N>
__device__ __forceinline__ void cp_wait() {
    asm volatile("cp.async.wait_group %0;\n" :: "n"(N));
}

// ---------------------------------------------------------------------------
// Prologue 1: fp32 -> fp16 (hidden -> g_ah)
// ---------------------------------------------------------------------------
__global__ void conv_half_kernel(const float* __restrict__ in,
                                 __half* __restrict__ out, int n8)
{
    int i = blockIdx.x * 256 + threadIdx.x;
    if (i < n8) {
        float4 v0 = reinterpret_cast<const float4*>(in)[2 * i];
        float4 v1 = reinterpret_cast<const float4*>(in)[2 * i + 1];
        __half2 h[4];
        h[0] = __floats2half2_rn(v0.x, v0.y);
        h[1] = __floats2half2_rn(v0.z, v0.w);
        h[2] = __floats2half2_rn(v1.x, v1.y);
        h[3] = __floats2half2_rn(v1.z, v1.w);
        reinterpret_cast<uint2*>(out)[2 * i]     = *reinterpret_cast<uint2*>(&h[0]);
        reinterpret_cast<uint2*>(out)[2 * i + 1] = *reinterpret_cast<uint2*>(&h[2]);
    }
}

// ---------------------------------------------------------------------------
// Prologue 2: W [K][N] fp32 -> Wt [N][K] fp16.  block (32,8)
// ---------------------------------------------------------------------------
__global__ void transpose_half_kernel(const float* __restrict__ W,
                                      __half* __restrict__ Wt, int K, int N)
{
    __shared__ float t[32][33];
    const int n0 = blockIdx.x * 32, k0 = blockIdx.y * 32;
    const int tx = threadIdx.x, ty = threadIdx.y;
#pragma unroll
    for (int j = 0; j < 4; j++)
        t[ty + 8 * j][tx] = W[(size_t)(k0 + ty + 8 * j) * N + n0 + tx];
    __syncthreads();
#pragma unroll
    for (int j = 0; j < 4; j++)
        Wt[(size_t)(n0 + ty + 8 * j) * K + k0 + tx] = __float2half_rn(t[tx][ty + 8 * j]);
}

// ---------------------------------------------------------------------------
// fp16 GEMM (round-14 verified shape): C[128m x 64n per CTA], 4 warps (64x32).
// k-chunk 64, 2-stage cp.async, ldmatrix x4, 4 CTAs/SM.
// Staging addresses hoisted: per-thread gmem row pointers + smem dsts
// computed ONCE; stage() does one ADD per cp.async.
// ---------------------------------------------------------------------------
constexpr int SAH = 72;                       // halfs per row
constexpr int GA  = 128 * SAH;                // A tile halfs
constexpr int GB  = 64 * SAH;                 // B tile halfs
constexpr int GSTG = GA + GB;                 // per stage halfs
constexpr int GSMEM_BYTES = 2 * GSTG * 2;     // 55296 B

__global__ __launch_bounds__(128, 4)
void gemm_h_kernel(const __half* __restrict__ A,  int lda,
                   const __half* __restrict__ Bt, int ldbt,
                   void* __restrict__ Cv,         int ldc,
                   int K, const float* __restrict__ bias, int out_half)
{
    extern __shared__ __align__(16) __half sg[];

    const int tid  = threadIdx.x;
    const int warp = tid >> 5, lane = tid & 31;
    const int g = lane >> 2, t = lane & 3;
    const int wm = (warp >> 1) * 64, wn = (warp & 1) * 32;
    const int m0 = blockIdx.y * 128, n0 = blockIdx.x * 64;

    A  += (size_t)m0 * lda;
    Bt += (size_t)n0 * ldbt;

    const int rowL = (lane & 7) + (lane & 8);
    const int colL = (lane & 16) ? 8 : 0;

    // ---- hoisted staging addresses ----
    const int sr = tid >> 3, sc = (tid & 7) * 8;   // per-thread row/col
    const __half* aSrc[8];
    const __half* bSrc[4];
    uint32_t aDst[8], bDst[4];
    {
        const uint32_t base = smem_u32(sg);
#pragma unroll
        for (int j = 0; j < 8; j++) {              // A rows: sr + 16j
            int r = sr + 16 * j;
            aSrc[j] = A + (size_t)r * lda + sc;
            aDst[j] = base + (r * SAH + sc) * 2;
        }
#pragma unroll
        for (int j = 0; j < 4; j++) {              // B rows: sr + 16j
            int r = sr + 16 * j;
            bSrc[j] = Bt + (size_t)r * ldbt + sc;
            bDst[j] = base + (GA + r * SAH + sc) * 2;
        }
    }

    float acc[4][4][4];
#pragma unroll
    for (int mi = 0; mi < 4; mi++)
#pragma unroll
        for (int nj = 0; nj < 4; nj++)
#pragma unroll
            for (int r = 0; r < 4; r++) acc[mi][nj][r] = 0.0f;

    auto stage = [&](int kt, int buf) {
        const int k0 = kt * 64;
        const uint32_t so = buf * (GSTG * 2);
#pragma unroll
        for (int j = 0; j < 8; j++)
            cp_async16s(aDst[j] + so, aSrc[j] + k0);
#pragma unroll
        for (int j = 0; j < 4; j++)
            cp_async16s(bDst[j] + so, bSrc[j] + k0);
        cp_commit();
    };

    stage(0, 0);
    const int KT = K / 64;

    for (int kt = 0; kt < KT; kt++) {
        const int buf = kt & 1;
        if (kt + 1 < KT) { stage(kt + 1, buf ^ 1); cp_wait<1>(); }
        else             { cp_wait<0>(); }
        __syncthreads();

        const __half* cA = sg + buf * GSTG;
        const __half* cB = cA + GA;
        uint32_t aAdr[4], bAdr[2];
#pragma unroll
        for (int mi = 0; mi < 4; mi++)
            aAdr[mi] = smem_u32(cA + (wm + mi * 16 + rowL) * SAH + colL);
#pragma unroll
        for (int njp = 0; njp < 2; njp++)
            bAdr[njp] = smem_u32(cB + (wn + njp * 16 + rowL) * SAH + colL);

#pragma unroll
        for (int kk = 0; kk < 64; kk += 16) {
            uint32_t a[4][4], bfr[2][4];
#pragma unroll
            for (int mi = 0; mi < 4; mi++)   ldm_x4(a[mi],   aAdr[mi]  + kk * 2);
#pragma unroll
            for (int njp = 0; njp < 2; njp++) ldm_x4(bfr[njp], bAdr[njp] + kk * 2);
#pragma unroll
            for (int mi = 0; mi < 4; mi++)
#pragma unroll
                for (int nj = 0; nj < 4; nj++)
                    mma16(acc[mi][nj], a[mi],
                          bfr[nj >> 1][nj & 1], bfr[nj >> 1][(nj & 1) + 2]);
        }
        __syncthreads();
    }

    // epilogue
#pragma unroll
    for (int mi = 0; mi < 4; mi++) {
#pragma unroll
        for (int nj = 0; nj < 4; nj++) {
            const int row = wm + mi * 16 + g;
            const int col = wn + nj * 8 + 2 * t;
            const float b0 = bias ? bias[n0 + col]     : 0.0f;
            const float b1 = bias ? bias[n0 + col + 1] : 0.0f;
            float v0 = acc[mi][nj][0] + b0, v1 = acc[mi][nj][1] + b1;
            float v2 = acc[mi][nj][2] + b0, v3 = acc[mi][nj][3] + b1;
            if (out_half) {
                __half* C16 = (__half*)Cv + (size_t)m0 * ldc + n0;
                *reinterpret_cast<__half2*>(C16 + (size_t)row * ldc + col) =
                    __floats2half2_rn(v0, v1);
                *reinterpret_cast<__half2*>(C16 + (size_t)(row + 8) * ldc + col) =
                    __floats2half2_rn(v2, v3);
            } else {
                float* C32 = (float*)Cv + (size_t)m0 * ldc + n0;
                *reinterpret_cast<float2*>(C32 + (size_t)row * ldc + col) =
                    make_float2(v0, v1);
                *reinterpret_cast<float2*>(C32 + (size_t)(row + 8) * ldc + col) =
                    make_float2(v2, v3);
            }
        }
    }
}

// ---------------------------------------------------------------------------
// Fused flash attention, fp16 (round-14 verified logic; staging addrs hoisted).
// ---------------------------------------------------------------------------
constexpr int FQ = 64;
constexpr int FP = 136;
constexpr int FLASH_SMEM_BYTES =
    (FQ * FP + 128 * FP + 128 * FP + FQ * FP) * 2 + (FQ + S) * 4;  // ~113 KB

__global__ __launch_bounds__(256, 2)
void flash_h_kernel(const float* __restrict__ mask)
{
    extern __shared__ __align__(16) __half smh[];
    __half* sQ = smh;                         // [64][136]
    __half* sK = sQ + FQ * FP;                // [128][136]
    __half* sV = sK + 128 * FP;               // [128][136]
    __half* sP = sV + 128 * FP;               // [64][136]
    float* sRow  = reinterpret_cast<float*>(sP + FQ * FP);
    float* sMask = sRow + FQ;

    const int tid  = threadIdx.x;
    const int warp = tid >> 5, lane = tid & 31;
    const int g = lane >> 2, t = lane & 3;
    const int wm = (warp >> 2) * 32;
    const int wn = (warp & 3) * 32;

    const int rowL = (lane & 7) + (lane & 8);
    const int colL = (lane & 16) ? 8 : 0;

    const int z  = blockIdx.y;
    const int b  = z >> 4;
    const int h  = z & 15;
    const int q0 = blockIdx.x * FQ;

    // ---- hoisted staging addresses (sr,sc shared by Q/K/V loops) ----
    const int sr = tid >> 4, sc = (tid & 15) * 8;  // 16 rows/pass, 128 cols
    const __half* __restrict__ Qg = g_qkv + (size_t)(b * S + q0) * H3 + h * D;
    const __half* kBase = g_qkv + (size_t)(b * S) * H3 + H     + h * D
                          + (size_t)sr * H3 + sc;
    const __half* vBase = g_qkv + (size_t)(b * S) * H3 + 2 * H + h * D
                          + (size_t)sr * H3 + sc;
    uint32_t kDst[8], vDst[8];
    {
#pragma unroll
        for (int j = 0; j < 8; j++) {
            int r = sr + 16 * j;
            kDst[j] = smem_u32(sK + r * FP + sc);
            vDst[j] = smem_u32(sV + r * FP + sc);
        }
    }
    const size_t kvStep = (size_t)16 * H3;         // 16 rows of H3

    // ---- prologue: async Q + K0, mask, rowsums ----
#pragma unroll
    for (int j = 0; j < 4; j++) {
        int r = sr + 16 * j;
        cp_async16s(smem_u32(sQ + r * FP + sc), Qg + (size_t)r * H3 + sc);
    }
#pragma unroll
    for (int j = 0; j < 8; j++)
        cp_async16s(kDst[j], kBase + (size_t)j * kvStep);
    cp_commit();
#pragma unroll
    for (int i = tid; i < S; i += 256) sMask[i] = mask[(size_t)b * S + i];
    if (tid < FQ) sRow[tid] = 0.0f;

    uint32_t aQAdr[2], aPAdr[2], bKAdr[2], bVAdr[2];
#pragma unroll
    for (int mi = 0; mi < 2; mi++) {
        aQAdr[mi] = smem_u32(sQ + (wm + mi * 16 + rowL) * FP + colL);
        aPAdr[mi] = smem_u32(sP + (wm + mi * 16 + rowL) * FP + colL);
    }
#pragma unroll
    for (int njp = 0; njp < 2; njp++) {
        bKAdr[njp] = smem_u32(sK + (wn + njp * 16 + rowL) * FP + colL);
        bVAdr[njp] = smem_u32(sV + rowL * FP + wn + njp * 16 + colL);
    }

    float oacc[2][4][4];
#pragma unroll
    for (int mi = 0; mi < 2; mi++)
#pragma unroll
        for (int nj = 0; nj < 4; nj++)
#pragma unroll
            for (int r = 0; r < 4; r++) oacc[mi][nj][r] = 0.0f;

    for (int jt = 0; jt < S / 128; jt++) {
        const int n0 = jt * 128;
        const size_t tileOff = (size_t)n0 * H3;

        cp_wait<0>();
        __syncthreads();

        // ---- prefetch V[jt] (overlaps QK) ----
#pragma unroll
        for (int j = 0; j < 8; j++)
            cp_async16s(vDst[j], vBase + tileOff + (size_t)j * kvStep);
        cp_commit();

        // ---- S = Q @ K^T ----
        float sacc[2][4][4];
#pragma unroll
        for (int mi = 0; mi < 2; mi++)
#pragma unroll
            for (int nj = 0; nj < 4; nj++)
#pragma unroll
                for (int r = 0; r < 4; r++) sacc[mi][nj][r] = 0.0f;

#pragma unroll
        for (int kk = 0; kk < D; kk += 16) {
            uint32_t a[2][4], bfr[2][4];
#pragma unroll
            for (int mi = 0; mi < 2; mi++)   ldm_x4(a[mi],   aQAdr[mi] + kk * 2);
#pragma unroll
            for (int njp = 0; njp < 2; njp++) ldm_x4(bfr[njp], bKAdr[njp] + kk * 2);
#pragma unroll
            for (int mi = 0; mi < 2; mi++)
#pragma unroll
                for (int nj = 0; nj < 4; nj++)
                    mma16(sacc[mi][nj], a[mi],
                          bfr[nj >> 1][nj & 1], bfr[nj >> 1][(nj & 1) + 2]);
        }

        // ---- P = exp(S*scale + mask) -> sP (fp16); rowsums ----
#pragma unroll
        for (int mi = 0; mi < 2; mi++) {
            const int r0 = wm + mi * 16 + g;
            float rp0 = 0.0f, rp1 = 0.0f;
#pragma unroll
            for (int nj = 0; nj < 4; nj++) {
                const int col = wn + nj * 8 + 2 * t;
                const float m0v = sMask[n0 + col];
                const float m1v = sMask[n0 + col + 1];
                float p00 = __expf(fmaf(sacc[mi][nj][0], SM_SCALE, m0v));
                float p01 = __expf(fmaf(sacc[mi][nj][1], SM_SCALE, m1v));
                float p10 = __expf(fmaf(sacc[mi][nj][2], SM_SCALE, m0v));
                float p11 = __expf(fmaf(sacc[mi][nj][3], SM_SCALE, m1v));
                rp0 += p00 + p01;
                rp1 += p10 + p11;
                *reinterpret_cast<__half2*>(&sP[r0 * FP + col]) =
                    __floats2half2_rn(p00, p01);
                *reinterpret_cast<__half2*>(&sP[(r0 + 8) * FP + col]) =
                    __floats2half2_rn(p10, p11);
            }
            rp0 += __shfl_xor_sync(0xffffffffu, rp0, 1);
            rp0 += __shfl_xor_sync(0xffffffffu, rp0, 2);
            rp1 += __shfl_xor_sync(0xffffffffu, rp1, 1);
            rp1 += __shfl_xor_sync(0xffffffffu, rp1, 2);
            if (t == 0) {
                atomicAdd(&sRow[r0], rp0);
                atomicAdd(&sRow[r0 + 8], rp1);
            }
        }

        cp_wait<0>();
        __syncthreads();

        // ---- prefetch K[jt+1] (overlaps PV) ----
        if (jt + 1 < S / 128) {
#pragma unroll
            for (int j = 0; j < 8; j++)
                cp_async16s(kDst[j], kBase + tileOff + (size_t)128 * H3
                                     + (size_t)j * kvStep);
            cp_commit();
        }

        // ---- O += P @ V : A=P plain-x4, B=V trans-x4 ----
#pragma unroll
        for (int kk = 0; kk < 128; kk += 16) {
            uint32_t a[2][4], bfr[2][4];
#pragma unroll
            for (int mi = 0; mi < 2; mi++) ldm_x4(a[mi], aPAdr[mi] + kk * 2);
#pragma unroll
            for (int njp = 0; njp < 2; njp++)
                ldm_x4_t(bfr[njp], bVAdr[njp] + kk * (FP * 2));
#pragma unroll
            for (int mi = 0; mi < 2; mi++)
#pragma unroll
                for (int nj = 0; nj < 4; nj++)
                    mma16(oacc[mi][nj], a[mi],
                          bfr[nj >> 1][(nj & 1) * 2], bfr[nj >> 1][(nj & 1) * 2 + 1]);
        }
    }

    // ---- epilogue: normalize, store ctx fp16 ----
#pragma unroll
    for (int mi = 0; mi < 2; mi++) {
        const int r0 = wm + mi * 16 + g;
        const float inv0 = 1.0f / sRow[r0];
        const float inv1 = 1.0f / sRow[r0 + 8];
#pragma unroll
        for (int nj = 0; nj < 4; nj++) {
            const int col = wn + nj * 8 + 2 * t;
            __half* dst = g_ctx + (size_t)(b * S + q0 + r0) * H + h * D + col;
            *reinterpret_cast<__half2*>(dst) =
                __floats2half2_rn(oacc[mi][nj][0] * inv0, oacc[mi][nj][1] * inv0);
            *reinterpret_cast<__half2*>(dst + (size_t)8 * H) =
                __floats2half2_rn(oacc[mi][nj][2] * inv1, oacc[mi][nj][3] * inv1);
        }
    }
}

// ---------------------------------------------------------------------------
// Launch
// ---------------------------------------------------------------------------
extern "C" void kernel_launch(void* const* d_in, const int* in_sizes, int n_in,
                              void* d_out, int out_size)
{
    const float* hidden = nullptr;
    const float* mask   = nullptr;
    const float* W_qkv  = nullptr;
    const float* b_qkv  = nullptr;
    const float* W_out  = nullptr;
    const float* b_out  = nullptr;

    for (int i = 0; i < n_in; i++) {
        switch (in_sizes[i]) {
            case 8388608:  hidden = (const float*)d_in[i]; break;
            case 4096:     mask   = (const float*)d_in[i]; break;
            case 12582912: W_qkv  = (const float*)d_in[i]; break;
            case 6144:     b_qkv  = (const float*)d_in[i]; break;
            case 4194304:  W_out  = (const float*)d_in[i]; break;
            case 2048:     b_out  = (const float*)d_in[i]; break;
            default: break;
        }
    }
    float* out = (float*)d_out;

    cudaFuncSetAttribute(flash_h_kernel,
                         cudaFuncAttributeMaxDynamicSharedMemorySize,
                         FLASH_SMEM_BYTES);
    cudaFuncSetAttribute(gemm_h_kernel,
                         cudaFuncAttributeMaxDynamicSharedMemorySize,
                         GSMEM_BYTES);

    __half* qkv_ptr;   cudaGetSymbolAddress((void**)&qkv_ptr,  g_qkv);
    __half* ctx_ptr;   cudaGetSymbolAddress((void**)&ctx_ptr,  g_ctx);
    __half* ah_ptr;    cudaGetSymbolAddress((void**)&ah_ptr,   g_ah);
    __half* wqkvt_ptr; cudaGetSymbolAddress((void**)&wqkvt_ptr, g_wqkvt);
    __half* woutt_ptr; cudaGetSymbolAddress((void**)&woutt_ptr, g_woutt);

    conv_half_kernel<<<(M * H / 8 + 255) / 256, 256>>>(hidden, ah_ptr, M * H / 8);
    transpose_half_kernel<<<dim3(H3 / 32, H / 32), dim3(32, 8)>>>(W_qkv, wqkvt_ptr, H, H3);
    transpose_half_kernel<<<dim3(H / 32, H / 32), dim3(32, 8)>>>(W_out, woutt_ptr, H, H);

    // QKV projection (fp16 output): 128x64 CTA kernel (round-14 verified shape)
    gemm_h_kernel<<<dim3(H3 / 64, M / 128), 128, GSMEM_BYTES>>>(
        ah_ptr, H, wqkvt_ptr, H, qkv_ptr, H3, H, b_qkv, 1);

    flash_h_kernel<<<dim3(S / FQ, B * NH), 256, FLASH_SMEM_BYTES>>>(mask);

    // output projection (fp32 output)
    gemm_h_kernel<<<dim3(H / 64, M / 128), 128, GSMEM_BYTES>>>(
        ctx_ptr, H, woutt_ptr, H, out, H, H, b_out, 0);
}

// round 17
// speedup vs baseline: 1.0360x; 1.0335x over previous
#include <cuda_runtime.h>
#include <cuda_fp16.h>
#include <cstdint>

// ---------------------------------------------------------------------------
// Problem constants
// ---------------------------------------------------------------------------
constexpr int B   = 2;
constexpr int S   = 2048;
constexpr int H   = 2048;
constexpr int NH  = 16;
constexpr int D   = 128;
constexpr int M   = B * S;     // 4096
constexpr int H3  = 3 * H;     // 6144
constexpr float SM_SCALE = 0.08838834764831845f;  // 1/sqrt(128)

// ---------------------------------------------------------------------------
// Scratch (fp16 operands; fp32 only at the final output)
// ---------------------------------------------------------------------------
__device__ __half g_qkv[(size_t)M * H3];     // [4096, 6144]
__device__ __half g_ctx[(size_t)M * H];      // [4096, 2048]
__device__ __half g_ah [(size_t)M * H];      // hidden -> fp16
__device__ __half g_wqkvt[(size_t)H3 * H];   // W_qkv^T [6144][2048]
__device__ __half g_woutt[(size_t)H * H];    // W_out^T [2048][2048]

// ---------------------------------------------------------------------------
// Helpers (baseline PTX only — compiles at compute_100)
// ---------------------------------------------------------------------------
__device__ __forceinline__ uint32_t smem_u32(const void* p) {
    uint32_t a;
    asm("{ .reg .u64 t; cvta.to.shared.u64 t, %1; cvt.u32.u64 %0, t; }"
        : "=r"(a) : "l"(p));
    return a;
}
// fp16 mma: D(16x8,f32) = A(16x16,f16) * B(16x8,f16) + C.  Scalar b operands.
__device__ __forceinline__ void mma16(float* d, const uint32_t* a,
                                      uint32_t b0, uint32_t b1) {
    asm volatile(
        "mma.sync.aligned.m16n8k16.row.col.f32.f16.f16.f32 "
        "{%0,%1,%2,%3}, {%4,%5,%6,%7}, {%8,%9}, {%0,%1,%2,%3};\n"
        : "+f"(d[0]), "+f"(d[1]), "+f"(d[2]), "+f"(d[3])
        : "r"(a[0]), "r"(a[1]), "r"(a[2]), "r"(a[3]), "r"(b0), "r"(b1));
}
// x4 ldmatrix b16.  lane addr = base + ((lane&7)+(lane&8))*stride + ((lane&16)?8:0)
// plain on [row][k]: A-frag (row=m) or plain-B pairs (row=n; n-oct even {r0,r2}, odd {r1,r3})
// trans on [k][col]: B-frag (d-oct even {r0,r1}, odd {r2,r3})
__device__ __forceinline__ void ldm_x4(uint32_t* r, uint32_t addr) {
    asm volatile("ldmatrix.sync.aligned.m8n8.x4.shared.b16 {%0,%1,%2,%3}, [%4];"
                 : "=r"(r[0]), "=r"(r[1]), "=r"(r[2]), "=r"(r[3]) : "r"(addr));
}
__device__ __forceinline__ void ldm_x4_t(uint32_t* r, uint32_t addr) {
    asm volatile("ldmatrix.sync.aligned.m8n8.x4.trans.shared.b16 {%0,%1,%2,%3}, [%4];"
                 : "=r"(r[0]), "=r"(r[1]), "=r"(r[2]), "=r"(r[3]) : "r"(addr));
}
__device__ __forceinline__ void cp_async16(void* smem, const void* gmem) {
    uint32_t s = (uint32_t)__cvta_generic_to_shared(smem);
    asm volatile("cp.async.cg.shared.global [%0], [%1], 16;\n" :: "r"(s), "l"(gmem));
}
__device__ __forceinline__ void cp_commit() { asm volatile("cp.async.commit_group;\n"); }
template <int N>
__device__ __forceinline__ void cp_wait() {
    asm volatile("cp.async.wait_group %0;\n" :: "n"(N));
}

// ---------------------------------------------------------------------------
// Merged prologue: one kernel, block (32,8)=256 thr, grid split by blockIdx:
//   [0, 4096)       : hidden fp32 -> fp16 (8 floats/thread)
//   [4096, 16384)   : W_qkv [2048][6144] -> Wqkv^T fp16
//   [16384, 20480)  : W_out [2048][2048] -> Wout^T fp16
// ---------------------------------------------------------------------------
__device__ __forceinline__ void transpose_body(
    const float* __restrict__ W, __half* __restrict__ Wt,
    int K, int N, int bx, int by)
{
    __shared__ float t[32][33];
    const int n0 = bx * 32, k0 = by * 32;
    const int tx = threadIdx.x, ty = threadIdx.y;
#pragma unroll
    for (int j = 0; j < 4; j++)
        t[ty + 8 * j][tx] = W[(size_t)(k0 + ty + 8 * j) * N + n0 + tx];
    __syncthreads();
#pragma unroll
    for (int j = 0; j < 4; j++)
        Wt[(size_t)(n0 + ty + 8 * j) * K + k0 + tx] = __float2half_rn(t[tx][ty + 8 * j]);
}

__global__ void prep_kernel(const float* __restrict__ hidden, __half* __restrict__ ah,
                            const float* __restrict__ Wq, __half* __restrict__ Wqt,
                            const float* __restrict__ Wo, __half* __restrict__ Wot)
{
    const int bid = blockIdx.x;
    const int tid = threadIdx.y * 32 + threadIdx.x;
    if (bid < 4096) {
        int i = bid * 256 + tid;                 // n8 = M*H/8 = 1048576
        float4 v0 = reinterpret_cast<const float4*>(hidden)[2 * i];
        float4 v1 = reinterpret_cast<const float4*>(hidden)[2 * i + 1];
        __half2 h[4];
        h[0] = __floats2half2_rn(v0.x, v0.y);
        h[1] = __floats2half2_rn(v0.z, v0.w);
        h[2] = __floats2half2_rn(v1.x, v1.y);
        h[3] = __floats2half2_rn(v1.z, v1.w);
        reinterpret_cast<uint2*>(ah)[2 * i]     = *reinterpret_cast<uint2*>(&h[0]);
        reinterpret_cast<uint2*>(ah)[2 * i + 1] = *reinterpret_cast<uint2*>(&h[2]);
    } else if (bid < 16384) {
        int r = bid - 4096;                      // 12288 blocks: 192 x 64
        transpose_body(Wq, Wqt, H, H3, r % 192, r / 192);
    } else {
        int r = bid - 16384;                     // 4096 blocks: 64 x 64
        transpose_body(Wo, Wot, H, H, r % 64, r / 64);
    }
}

// ---------------------------------------------------------------------------
// fp16 GEMM (round-14 verified shape): C[128m x 64n per CTA], 4 warps (64x32).
// k-chunk 64, 2-stage cp.async, ldmatrix x4, 4 CTAs/SM.
// SINGLE barrier per chunk:  wait -> sync -> prefetch(kt+1) -> compute.
//   The sync (a) publishes all threads' stage(kt) copies and (b) retires all
//   readers of buf^1 (compute kt-1), making the prefetch write safe.
// ---------------------------------------------------------------------------
constexpr int SAH = 72;                       // halfs per row
constexpr int GA  = 128 * SAH;                // A tile halfs
constexpr int GB  = 64 * SAH;                 // B tile halfs
constexpr int GSTG = GA + GB;                 // per stage halfs
constexpr int GSMEM_BYTES = 2 * GSTG * 2;     // 55296 B

__global__ __launch_bounds__(128, 4)
void gemm_h_kernel(const __half* __restrict__ A,  int lda,
                   const __half* __restrict__ Bt, int ldbt,
                   void* __restrict__ Cv,         int ldc,
                   int K, const float* __restrict__ bias, int out_half)
{
    extern __shared__ __align__(16) __half sg[];

    const int tid  = threadIdx.x;
    const int warp = tid >> 5, lane = tid & 31;
    const int g = lane >> 2, t = lane & 3;
    const int wm = (warp >> 1) * 64, wn = (warp & 1) * 32;
    const int m0 = blockIdx.y * 128, n0 = blockIdx.x * 64;

    A  += (size_t)m0 * lda;
    Bt += (size_t)n0 * ldbt;

    const int rowL = (lane & 7) + (lane & 8);
    const int colL = (lane & 16) ? 8 : 0;

    float acc[4][4][4];
#pragma unroll
    for (int mi = 0; mi < 4; mi++)
#pragma unroll
        for (int nj = 0; nj < 4; nj++)
#pragma unroll
            for (int r = 0; r < 4; r++) acc[mi][nj][r] = 0.0f;

    auto stage = [&](int kt, int buf) {
        __half* dA = sg + buf * GSTG;
        __half* dB = dA + GA;
        const int k0 = kt * 64;
#pragma unroll
        for (int j = 0; j < 8; j++) {              // A: 1024 chunks
            int idx = tid + j * 128;
            int r = idx >> 3, c = (idx & 7) * 8;
            cp_async16(&dA[r * SAH + c], A + (size_t)r * lda + k0 + c);
        }
#pragma unroll
        for (int j = 0; j < 4; j++) {              // B: 512 chunks
            int idx = tid + j * 128;
            int r = idx >> 3, c = (idx & 7) * 8;
            cp_async16(&dB[r * SAH + c], Bt + (size_t)r * ldbt + k0 + c);
        }
        cp_commit();
    };

    stage(0, 0);
    const int KT = K / 64;

    for (int kt = 0; kt < KT; kt++) {
        const int buf = kt & 1;
        cp_wait<0>();              // stage(kt) complete (only pending group)
        __syncthreads();           // publish buf; retire readers of buf^1
        if (kt + 1 < KT) stage(kt + 1, buf ^ 1);   // overlaps compute below

        const __half* cA = sg + buf * GSTG;
        const __half* cB = cA + GA;
        uint32_t aAdr[4], bAdr[2];
#pragma unroll
        for (int mi = 0; mi < 4; mi++)
            aAdr[mi] = smem_u32(cA + (wm + mi * 16 + rowL) * SAH + colL);
#pragma unroll
        for (int njp = 0; njp < 2; njp++)
            bAdr[njp] = smem_u32(cB + (wn + njp * 16 + rowL) * SAH + colL);

#pragma unroll
        for (int kk = 0; kk < 64; kk += 16) {
            uint32_t a[4][4], bfr[2][4];
#pragma unroll
            for (int mi = 0; mi < 4; mi++)   ldm_x4(a[mi],   aAdr[mi]  + kk * 2);
#pragma unroll
            for (int njp = 0; njp < 2; njp++) ldm_x4(bfr[njp], bAdr[njp] + kk * 2);
#pragma unroll
            for (int mi = 0; mi < 4; mi++)
#pragma unroll
                for (int nj = 0; nj < 4; nj++)
                    mma16(acc[mi][nj], a[mi],
                          bfr[nj >> 1][nj & 1], bfr[nj >> 1][(nj & 1) + 2]);
        }
    }

    // epilogue
#pragma unroll
    for (int mi = 0; mi < 4; mi++) {
#pragma unroll
        for (int nj = 0; nj < 4; nj++) {
            const int row = wm + mi * 16 + g;
            const int col = wn + nj * 8 + 2 * t;
            const float b0 = bias ? bias[n0 + col]     : 0.0f;
            const float b1 = bias ? bias[n0 + col + 1] : 0.0f;
            float v0 = acc[mi][nj][0] + b0, v1 = acc[mi][nj][1] + b1;
            float v2 = acc[mi][nj][2] + b0, v3 = acc[mi][nj][3] + b1;
            if (out_half) {
                __half* C16 = (__half*)Cv + (size_t)m0 * ldc + n0;
                *reinterpret_cast<__half2*>(C16 + (size_t)row * ldc + col) =
                    __floats2half2_rn(v0, v1);
                *reinterpret_cast<__half2*>(C16 + (size_t)(row + 8) * ldc + col) =
                    __floats2half2_rn(v2, v3);
            } else {
                float* C32 = (float*)Cv + (size_t)m0 * ldc + n0;
                *reinterpret_cast<float2*>(C32 + (size_t)row * ldc + col) =
                    make_float2(v0, v1);
                *reinterpret_cast<float2*>(C32 + (size_t)(row + 8) * ldc + col) =
                    make_float2(v2, v3);
            }
        }
    }
}

// ---------------------------------------------------------------------------
// Fused flash attention, fp16 (round-14 verified; byte-identical logic).
// ---------------------------------------------------------------------------
constexpr int FQ = 64;
constexpr int FP = 136;
constexpr int FLASH_SMEM_BYTES =
    (FQ * FP + 128 * FP + 128 * FP + FQ * FP) * 2 + (FQ + S) * 4;  // ~113 KB

__global__ __launch_bounds__(256, 2)
void flash_h_kernel(const float* __restrict__ mask)
{
    extern __shared__ __align__(16) __half smh[];
    __half* sQ = smh;
    __half* sK = sQ + FQ * FP;
    __half* sV = sK + 128 * FP;
    __half* sP = sV + 128 * FP;
    float* sRow  = reinterpret_cast<float*>(sP + FQ * FP);
    float* sMask = sRow + FQ;

    const int tid  = threadIdx.x;
    const int warp = tid >> 5, lane = tid & 31;
    const int g = lane >> 2, t = lane & 3;
    const int wm = (warp >> 2) * 32;
    const int wn = (warp & 3) * 32;

    const int rowL = (lane & 7) + (lane & 8);
    const int colL = (lane & 16) ? 8 : 0;

    const int z  = blockIdx.y;
    const int b  = z >> 4;
    const int h  = z & 15;
    const int q0 = blockIdx.x * FQ;

    const __half* __restrict__ Qg = g_qkv + (size_t)(b * S + q0) * H3 + h * D;

#pragma unroll
    for (int j = 0; j < 4; j++) {
        int idx = tid + j * 256;
        int r = idx >> 4, c = (idx & 15) * 8;
        cp_async16(&sQ[r * FP + c], Qg + (size_t)r * H3 + c);
    }
    {
        const __half* Kg0 = g_qkv + (size_t)(b * S) * H3 + H + h * D;
#pragma unroll
        for (int j = 0; j < 8; j++) {
            int idx = tid + j * 256;
            int r = idx >> 4, c = (idx & 15) * 8;
            cp_async16(&sK[r * FP + c], Kg0 + (size_t)r * H3 + c);
        }
    }
    cp_commit();
#pragma unroll
    for (int i = tid; i < S; i += 256) sMask[i] = mask[(size_t)b * S + i];
    if (tid < FQ) sRow[tid] = 0.0f;

    uint32_t aQAdr[2], aPAdr[2], bKAdr[2], bVAdr[2];
#pragma unroll
    for (int mi = 0; mi < 2; mi++) {
        aQAdr[mi] = smem_u32(sQ + (wm + mi * 16 + rowL) * FP + colL);
        aPAdr[mi] = smem_u32(sP + (wm + mi * 16 + rowL) * FP + colL);
    }
#pragma unroll
    for (int njp = 0; njp < 2; njp++) {
        bKAdr[njp] = smem_u32(sK + (wn + njp * 16 + rowL) * FP + colL);
        bVAdr[njp] = smem_u32(sV + rowL * FP + wn + njp * 16 + colL);
    }

    float oacc[2][4][4];
#pragma unroll
    for (int mi = 0; mi < 2; mi++)
#pragma unroll
        for (int nj = 0; nj < 4; nj++)
#pragma unroll
            for (int r = 0; r < 4; r++) oacc[mi][nj][r] = 0.0f;

    for (int jt = 0; jt < S / 128; jt++) {
        const int n0 = jt * 128;

        cp_wait<0>();
        __syncthreads();

        {
            const __half* Vg = g_qkv + (size_t)(b * S + n0) * H3 + 2 * H + h * D;
#pragma unroll
            for (int j = 0; j < 8; j++) {
                int idx = tid + j * 256;
                int r = idx >> 4, c = (idx & 15) * 8;
                cp_async16(&sV[r * FP + c], Vg + (size_t)r * H3 + c);
            }
            cp_commit();
        }

        float sacc[2][4][4];
#pragma unroll
        for (int mi = 0; mi < 2; mi++)
#pragma unroll
            for (int nj = 0; nj < 4; nj++)
#pragma unroll
                for (int r = 0; r < 4; r++) sacc[mi][nj][r] = 0.0f;

#pragma unroll
        for (int kk = 0; kk < D; kk += 16) {
            uint32_t a[2][4], bfr[2][4];
#pragma unroll
            for (int mi = 0; mi < 2; mi++)   ldm_x4(a[mi],   aQAdr[mi] + kk * 2);
#pragma unroll
            for (int njp = 0; njp < 2; njp++) ldm_x4(bfr[njp], bKAdr[njp] + kk * 2);
#pragma unroll
            for (int mi = 0; mi < 2; mi++)
#pragma unroll
                for (int nj = 0; nj < 4; nj++)
                    mma16(sacc[mi][nj], a[mi],
                          bfr[nj >> 1][nj & 1], bfr[nj >> 1][(nj & 1) + 2]);
        }

#pragma unroll
        for (int mi = 0; mi < 2; mi++) {
            const int r0 = wm + mi * 16 + g;
            float rp0 = 0.0f, rp1 = 0.0f;
#pragma unroll
            for (int nj = 0; nj < 4; nj++) {
                const int col = wn + nj * 8 + 2 * t;
                const float m0v = sMask[n0 + col];
                const float m1v = sMask[n0 + col + 1];
                float p00 = __expf(fmaf(sacc[mi][nj][0], SM_SCALE, m0v));
                float p01 = __expf(fmaf(sacc[mi][nj][1], SM_SCALE, m1v));
                float p10 = __expf(fmaf(sacc[mi][nj][2], SM_SCALE, m0v));
                float p11 = __expf(fmaf(sacc[mi][nj][3], SM_SCALE, m1v));
                rp0 += p00 + p01;
                rp1 += p10 + p11;
                *reinterpret_cast<__half2*>(&sP[r0 * FP + col]) =
                    __floats2half2_rn(p00, p01);
                *reinterpret_cast<__half2*>(&sP[(r0 + 8) * FP + col]) =
                    __floats2half2_rn(p10, p11);
            }
            rp0 += __shfl_xor_sync(0xffffffffu, rp0, 1);
            rp0 += __shfl_xor_sync(0xffffffffu, rp0, 2);
            rp1 += __shfl_xor_sync(0xffffffffu, rp1, 1);
            rp1 += __shfl_xor_sync(0xffffffffu, rp1, 2);
            if (t == 0) {
                atomicAdd(&sRow[r0], rp0);
                atomicAdd(&sRow[r0 + 8], rp1);
            }
        }

        cp_wait<0>();
        __syncthreads();

        if (jt + 1 < S / 128) {
            const __half* Kg = g_qkv + (size_t)(b * S + n0 + 128) * H3 + H + h * D;
#pragma unroll
            for (int j = 0; j < 8; j++) {
                int idx = tid + j * 256;
                int r = idx >> 4, c = (idx & 15) * 8;
                cp_async16(&sK[r * FP + c], Kg + (size_t)r * H3 + c);
            }
            cp_commit();
        }

#pragma unroll
        for (int kk = 0; kk < 128; kk += 16) {
            uint32_t a[2][4], bfr[2][4];
#pragma unroll
            for (int mi = 0; mi < 2; mi++) ldm_x4(a[mi], aPAdr[mi] + kk * 2);
#pragma unroll
            for (int njp = 0; njp < 2; njp++)
                ldm_x4_t(bfr[njp], bVAdr[njp] + kk * (FP * 2));
#pragma unroll
            for (int mi = 0; mi < 2; mi++)
#pragma unroll
                for (int nj = 0; nj < 4; nj++)
                    mma16(oacc[mi][nj], a[mi],
                          bfr[nj >> 1][(nj & 1) * 2], bfr[nj >> 1][(nj & 1) * 2 + 1]);
        }
    }

#pragma unroll
    for (int mi = 0; mi < 2; mi++) {
        const int r0 = wm + mi * 16 + g;
        const float inv0 = 1.0f / sRow[r0];
        const float inv1 = 1.0f / sRow[r0 + 8];
#pragma unroll
        for (int nj = 0; nj < 4; nj++) {
            const int col = wn + nj * 8 + 2 * t;
            __half* dst = g_ctx + (size_t)(b * S + q0 + r0) * H + h * D + col;
            *reinterpret_cast<__half2*>(dst) =
                __floats2half2_rn(oacc[mi][nj][0] * inv0, oacc[mi][nj][1] * inv0);
            *reinterpret_cast<__half2*>(dst + (size_t)8 * H) =
                __floats2half2_rn(oacc[mi][nj][2] * inv1, oacc[mi][nj][3] * inv1);
        }
    }
}

// ---------------------------------------------------------------------------
// Launch
// ---------------------------------------------------------------------------
extern "C" void kernel_launch(void* const* d_in, const int* in_sizes, int n_in,
                              void* d_out, int out_size)
{
    const float* hidden = nullptr;
    const float* mask   = nullptr;
    const float* W_qkv  = nullptr;
    const float* b_qkv  = nullptr;
    const float* W_out  = nullptr;
    const float* b_out  = nullptr;

    for (int i = 0; i < n_in; i++) {
        switch (in_sizes[i]) {
            case 8388608:  hidden = (const float*)d_in[i]; break;
            case 4096:     mask   = (const float*)d_in[i]; break;
            case 12582912: W_qkv  = (const float*)d_in[i]; break;
            case 6144:     b_qkv  = (const float*)d_in[i]; break;
            case 4194304:  W_out  = (const float*)d_in[i]; break;
            case 2048:     b_out  = (const float*)d_in[i]; break;
            default: break;
        }
    }
    float* out = (float*)d_out;

    cudaFuncSetAttribute(flash_h_kernel,
                         cudaFuncAttributeMaxDynamicSharedMemorySize,
                         FLASH_SMEM_BYTES);
    cudaFuncSetAttribute(gemm_h_kernel,
                         cudaFuncAttributeMaxDynamicSharedMemorySize,
                         GSMEM_BYTES);

    __half* qkv_ptr;   cudaGetSymbolAddress((void**)&qkv_ptr,  g_qkv);
    __half* ctx_ptr;   cudaGetSymbolAddress((void**)&ctx_ptr,  g_ctx);
    __half* ah_ptr;    cudaGetSymbolAddress((void**)&ah_ptr,   g_ah);
    __half* wqkvt_ptr; cudaGetSymbolAddress((void**)&wqkvt_ptr, g_wqkvt);
    __half* woutt_ptr; cudaGetSymbolAddress((void**)&woutt_ptr, g_woutt);

    // merged prologue: conv(4096) + transW_qkv(12288) + transW_out(4096)
    prep_kernel<<<20480, dim3(32, 8)>>>(hidden, ah_ptr,
                                        W_qkv, wqkvt_ptr,
                                        W_out, woutt_ptr);

    // QKV projection (fp16 output)
    gemm_h_kernel<<<dim3(H3 / 64, M / 128), 128, GSMEM_BYTES>>>(
        ah_ptr, H, wqkvt_ptr, H, qkv_ptr, H3, H, b_qkv, 1);

    flash_h_kernel<<<dim3(S / FQ, B * NH), 256, FLASH_SMEM_BYTES>>>(mask);

    // output projection (fp32 output)
    gemm_h_kernel<<<dim3(H / 64, M / 128), 128, GSMEM_BYTES>>>(
        ctx_ptr, H, woutt_ptr, H, out, H, H, b_out, 0);
}